// round 13
// baseline (speedup 1.0000x reference)
#include <cuda_runtime.h>
#include <cstdint>

// AggrSum: out[n, :] = sum over edges e with X_node[e] == n of H[e, :]
// H: [2M, 32] f32, X_node: [2M] i32 (harness downcast), out: [100K, 32] f32
//
// R13: RED scatter into an invariant-zeroed persistent accumulator + fused
// finalize (out = acc; acc = 0). Removes the serialized 12.8MB memset from
// the critical path (finalize streams 38MB in ~1.4us). Scatter: UNROLL=6 at
// unchanged 6 CTA/SM occupancy for more MLP (R11 was U=4 @ 30 regs).
//
// Invariant: g_acc is all-zeros before and after every kernel_launch call
// (BSS-zeroed at module load; finalize re-zeroes what scatter touched).
// Same replay-safe pattern as the R7-R9 g_count reset (passed verification).
//
// Measured structure rationale (R2-R12): scatter beats CSR-gather (random
// 128B row reads cap ~55% DRAM + build cost); binder is the L2 RMW path
// (~520MB LTS traffic + 83K atomic slice-cycles), insensitive to occupancy
// 42-85% and to LDG-vs-TMA load path.

static constexpr int D = 32;
static constexpr int VEC = 4;
static constexpr int LANES = D / VEC;     // 8 float4s per edge row
static constexpr int UNROLL = 6;
static constexpr int THREADS = 256;
static constexpr int MAX_NODES = 1 << 17; // 131072 >= 100K

__device__ float4 g_acc[(size_t)MAX_NODES * LANES];   // 16.8 MB, BSS-zeroed

__device__ __forceinline__ void red_add_v4(float* dst, float4 v) {
    asm volatile("red.global.add.v4.f32 [%0], {%1, %2, %3, %4};"
                 :: "l"(dst), "f"(v.x), "f"(v.y), "f"(v.z), "f"(v.w)
                 : "memory");
}

__global__ void __launch_bounds__(THREADS, 6)
scatter_add_kernel(const float4* __restrict__ H,
                   const int* __restrict__ idx,
                   float* __restrict__ dst,       // g_acc (main) or d_out (fallback)
                   int nitems, int node_num) {
    const int T = gridDim.x * blockDim.x;   // stride between a thread's items
    const int t = blockIdx.x * blockDim.x + threadIdx.x;

    if (t + (UNROLL - 1) * T < nitems) {
        // Fast path: UNROLL independent LDG.128 + broadcast idx loads
        // front-batched, then UNROLL REDs.
        float4 v[UNROLL];
        int    n[UNROLL];
        #pragma unroll
        for (int k = 0; k < UNROLL; k++) v[k] = __ldcs(&H[t + k * T]);
        #pragma unroll
        for (int k = 0; k < UNROLL; k++) n[k] = __ldg(&idx[(t + k * T) >> 3]);
        #pragma unroll
        for (int k = 0; k < UNROLL; k++) {
            if ((unsigned)n[k] < (unsigned)node_num)
                red_add_v4(dst + (size_t)(unsigned)n[k] * D
                               + ((t + k * T) & (LANES - 1)) * VEC, v[k]);
        }
    } else {
        #pragma unroll
        for (int k = 0; k < UNROLL; k++) {
            int i = t + k * T;
            if (i < nitems) {
                float4 v = __ldcs(&H[i]);
                int n = __ldg(&idx[i >> 3]);
                if ((unsigned)n < (unsigned)node_num)
                    red_add_v4(dst + (size_t)(unsigned)n * D + (i & (LANES - 1)) * VEC, v);
            }
        }
    }
}

// out = acc; acc = 0  (restores the zero-invariant for the next call/replay)
__global__ void finalize_kernel(float4* __restrict__ out4, int n4) {
    int i = blockIdx.x * blockDim.x + threadIdx.x;
    if (i < n4) {
        out4[i] = g_acc[i];
        g_acc[i] = make_float4(0.f, 0.f, 0.f, 0.f);
    }
}

extern "C" void kernel_launch(void* const* d_in, const int* in_sizes, int n_in,
                              void* d_out, int out_size) {
    const float4* H = (const float4*)d_in[0];
    const int* idx = (const int*)d_in[1];

    int num_edges = in_sizes[0] / D;
    int node_num = out_size / D;
    int nitems = num_edges * LANES;   // 16M float4 items at the bench shape

    long long want = ((long long)nitems + UNROLL - 1) / UNROLL;
    int blocks = (int)((want + THREADS - 1) / THREADS);

    if (node_num <= MAX_NODES) {
        // Main path: scatter into invariant-zeroed g_acc, then finalize.
        void* accp = nullptr;
        cudaGetSymbolAddress(&accp, g_acc);
        scatter_add_kernel<<<blocks, THREADS>>>(H, idx, (float*)accp,
                                                nitems, node_num);
        int n4 = out_size / VEC;
        int fblocks = (n4 + THREADS - 1) / THREADS;
        finalize_kernel<<<fblocks, THREADS>>>((float4*)d_out, n4);
    } else {
        // Fallback: memset + direct scatter (R12 shape).
        cudaMemsetAsync(d_out, 0, (size_t)out_size * sizeof(float));
        scatter_add_kernel<<<blocks, THREADS>>>(H, idx, (float*)d_out,
                                                nitems, node_num);
    }
}

// round 14
// speedup vs baseline: 1.0347x; 1.0347x over previous
#include <cuda_runtime.h>
#include <cstdint>

// AggrSum: out[n, :] = sum over edges e with X_node[e] == n of H[e, :]
// H: [2M, 32] f32, X_node: [2M] i32 (harness downcast), out: [100K, 32] f32
//
// R14: recombination of measured-best components.
//  - Scatter: UNROLL=6 front-batched RED scatter (R13 run: ~54.8us, vs 57.0
//    at U=4) writing d_out directly.
//  - Zeroing: cudaMemsetAsync graph node (~2.3us; cheaper than zero-kernel
//    3.3us and accumulator+finalize 8.2us, both measured).
//
// Structure rationale (measured R2-R13): RED scatter beats CSR-gather
// (random 128B row reads cap ~55% DRAM + ~20us build); binder is the L2 RMW
// path (~520MB LTS traffic + ~83K atomic slice-cycles), insensitive to
// occupancy 42-85% and LDG-vs-TMA load path. RED.v4 is width-maximal and
// the warp's RED footprint is sector-minimal (8 lanes per 128B node row).

static constexpr int D = 32;
static constexpr int VEC = 4;
static constexpr int LANES = D / VEC;     // 8 float4s per edge row
static constexpr int UNROLL = 6;
static constexpr int THREADS = 256;

__device__ __forceinline__ void red_add_v4(float* dst, float4 v) {
    asm volatile("red.global.add.v4.f32 [%0], {%1, %2, %3, %4};"
                 :: "l"(dst), "f"(v.x), "f"(v.y), "f"(v.z), "f"(v.w)
                 : "memory");
}

__global__ void __launch_bounds__(THREADS, 6)
scatter_add_kernel(const float4* __restrict__ H,
                   const int* __restrict__ idx,
                   float* __restrict__ out,
                   int nitems, int node_num) {
    const int T = gridDim.x * blockDim.x;   // stride between a thread's items
    const int t = blockIdx.x * blockDim.x + threadIdx.x;

    if (t + (UNROLL - 1) * T < nitems) {
        // Fast path: UNROLL independent LDG.128 + broadcast idx loads
        // front-batched, then UNROLL REDs.
        float4 v[UNROLL];
        int    n[UNROLL];
        #pragma unroll
        for (int k = 0; k < UNROLL; k++) v[k] = __ldcs(&H[t + k * T]);
        #pragma unroll
        for (int k = 0; k < UNROLL; k++) n[k] = __ldg(&idx[(t + k * T) >> 3]);
        #pragma unroll
        for (int k = 0; k < UNROLL; k++) {
            if ((unsigned)n[k] < (unsigned)node_num)
                red_add_v4(out + (size_t)(unsigned)n[k] * D
                               + ((t + k * T) & (LANES - 1)) * VEC, v[k]);
        }
    } else {
        // Tail (not taken when nitems % (T*UNROLL) == 0).
        #pragma unroll
        for (int k = 0; k < UNROLL; k++) {
            int i = t + k * T;
            if (i < nitems) {
                float4 v = __ldcs(&H[i]);
                int n = __ldg(&idx[i >> 3]);
                if ((unsigned)n < (unsigned)node_num)
                    red_add_v4(out + (size_t)(unsigned)n * D + (i & (LANES - 1)) * VEC, v);
            }
        }
    }
}

extern "C" void kernel_launch(void* const* d_in, const int* in_sizes, int n_in,
                              void* d_out, int out_size) {
    const float4* H = (const float4*)d_in[0];
    const int* idx = (const int*)d_in[1];
    float* out = (float*)d_out;

    int num_edges = in_sizes[0] / D;
    int node_num = out_size / D;
    int nitems = num_edges * LANES;   // 16M float4 items at the bench shape

    // 1) zero output (poisoned to 0xAA): graph memset node.
    cudaMemsetAsync(d_out, 0, (size_t)out_size * sizeof(float));

    // 2) scatter-add: exact cover, one 6-item batch per thread.
    {
        long long want = ((long long)nitems + UNROLL - 1) / UNROLL;
        int blocks = (int)((want + THREADS - 1) / THREADS);
        scatter_add_kernel<<<blocks, THREADS>>>(H, idx, out, nitems, node_num);
    }
}

// round 16
// speedup vs baseline: 1.0718x; 1.0359x over previous
#include <cuda_runtime.h>
#include <cstdint>

// AggrSum: out[n, :] = sum over edges e with X_node[e] == n of H[e, :]
// H: [2M, 32] f32, X_node: [2M] i32 (harness downcast), out: [100K, 32] f32
//
// R16 (final form): R12's proven config + L2-policy polish.
//  - cudaMemsetAsync graph node for zeroing (measured cheapest: 2.3us vs
//    zero-kernel 3.3us vs accumulator+finalize 8.2us).
//  - UNROLL=4 front-batched RED.v4 scatter, exact cover, 30 regs, high occ
//    (measured 57.0us; U=6/U=8 lose via occupancy, per R4/R14).
//  - Both H and idx streamed with __ldcs (evict-first) so L2 stays dedicated
//    to the atomic-resident out (12.8MB).
//
// Why this is the floor (measured R2-R15):
//  - red.v4.f32 is HW-max width (ptxas rejects .v8) -> 16M atomic ops
//    irreducible; L2 atomic slice-cycles + LTS RMW traffic bind at ~57us,
//    insensitive to occupancy 42-85%, MLP 2-8, and LDG-vs-TMA load path.
//  - CSR gather loses: random 128B row reads cap ~55% DRAM + ~20us build.

static constexpr int D = 32;
static constexpr int VEC = 4;
static constexpr int LANES = D / VEC;   // 8 float4s per edge row
static constexpr int UNROLL = 4;
static constexpr int THREADS = 256;

__device__ __forceinline__ void red_add_v4(float* dst, float4 v) {
    asm volatile("red.global.add.v4.f32 [%0], {%1, %2, %3, %4};"
                 :: "l"(dst), "f"(v.x), "f"(v.y), "f"(v.z), "f"(v.w)
                 : "memory");
}

__global__ void __launch_bounds__(THREADS, 7)
scatter_add_kernel(const float4* __restrict__ H,
                   const int* __restrict__ idx,
                   float* __restrict__ out,
                   int nitems, int node_num) {
    const int T = gridDim.x * blockDim.x;   // stride between a thread's items
    const int t = blockIdx.x * blockDim.x + threadIdx.x;

    if (t + 3 * T < nitems) {
        // Fast path (always taken at the bench shape): 4 independent
        // LDG.128 + 4 broadcast idx loads front-batched, then 4 REDs.
        float4 v0 = __ldcs(&H[t]);
        float4 v1 = __ldcs(&H[t + T]);
        float4 v2 = __ldcs(&H[t + 2 * T]);
        float4 v3 = __ldcs(&H[t + 3 * T]);
        int n0 = __ldcs(&idx[t >> 3]);
        int n1 = __ldcs(&idx[(t + T) >> 3]);
        int n2 = __ldcs(&idx[(t + 2 * T) >> 3]);
        int n3 = __ldcs(&idx[(t + 3 * T) >> 3]);

        if ((unsigned)n0 < (unsigned)node_num)
            red_add_v4(out + (size_t)(unsigned)n0 * D + (t & (LANES - 1)) * VEC, v0);
        if ((unsigned)n1 < (unsigned)node_num)
            red_add_v4(out + (size_t)(unsigned)n1 * D + ((t + T) & (LANES - 1)) * VEC, v1);
        if ((unsigned)n2 < (unsigned)node_num)
            red_add_v4(out + (size_t)(unsigned)n2 * D + ((t + 2 * T) & (LANES - 1)) * VEC, v2);
        if ((unsigned)n3 < (unsigned)node_num)
            red_add_v4(out + (size_t)(unsigned)n3 * D + ((t + 3 * T) & (LANES - 1)) * VEC, v3);
    } else {
        // Tail (not taken when nitems % (T*UNROLL) == 0).
        #pragma unroll
        for (int k = 0; k < UNROLL; k++) {
            int i = t + k * T;
            if (i < nitems) {
                float4 v = __ldcs(&H[i]);
                int n = __ldcs(&idx[i >> 3]);
                if ((unsigned)n < (unsigned)node_num)
                    red_add_v4(out + (size_t)(unsigned)n * D + (i & (LANES - 1)) * VEC, v);
            }
        }
    }
}

extern "C" void kernel_launch(void* const* d_in, const int* in_sizes, int n_in,
                              void* d_out, int out_size) {
    const float4* H = (const float4*)d_in[0];
    const int* idx = (const int*)d_in[1];
    float* out = (float*)d_out;

    int num_edges = in_sizes[0] / D;
    int node_num = out_size / D;
    int nitems = num_edges * LANES;   // 16M float4 items at the bench shape

    // 1) zero output (poisoned to 0xAA): graph memset node.
    cudaMemsetAsync(d_out, 0, (size_t)out_size * sizeof(float));

    // 2) scatter-add: exact cover, one 4-item batch per thread.
    {
        long long want = ((long long)nitems + UNROLL - 1) / UNROLL;
        int blocks = (int)((want + THREADS - 1) / THREADS);
        scatter_add_kernel<<<blocks, THREADS>>>(H, idx, out, nitems, node_num);
    }
}